// round 13
// baseline (speedup 1.0000x reference)
#include <cuda_runtime.h>
#include <cuda_bf16.h>
#include <cstdint>

#define BB 64
#define SS 2048
#define DD 1024
#define SPLITS 32
#define S_PER (SS / SPLITS)   // 64
#define WCNT (S_PER / 32)     // 2 warps cover the slice mask

// Scratch (allocation-free rule: __device__ globals)
__device__ int   g_scnt[SPLITS * BB];              // per-slice nonzero counts
__device__ float g_partial[SPLITS * BB * DD];      // 8 MB unweighted partials
__device__ int   g_arrive[BB];                     // zero-init; self-resetting

// ---------------------------------------------------------------------------
// Single fused kernel, SPLITS=32 -> 2048 tiles (~2 waves, good backfill).
// Gather phase measured at its pattern ceiling (~5.6TB/s on 4KB-granule
// 50%-hole gather); this round shaves fixed overheads: one-ballot prologue,
// L2-batched combine with own-partial kept in registers.
// grid = (SPLITS, BB), block = 256, one float4 of D per thread.
// ---------------------------------------------------------------------------
__global__ void __launch_bounds__(256)
pool_kernel(const float* __restrict__ hidden, const int* __restrict__ mask,
            float* __restrict__ out) {
    const int b     = blockIdx.y;
    const int split = blockIdx.x;
    const int s0    = split * S_PER;
    const int tid   = threadIdx.x;

    __shared__ short    s_idx[S_PER];
    __shared__ unsigned s_ball[WCNT];
    __shared__ int      s_ticket;

    // ---- one-ballot prologue: slice mask -> shared ballots -> compaction ----
    const int warp = tid >> 5, lane = tid & 31;
    if (tid < S_PER) {
        const int mv = mask[b * SS + s0 + tid];
        const unsigned ball = __ballot_sync(0xFFFFFFFFu, mv != 0);
        if (lane == 0) s_ball[warp] = ball;
    }
    __syncthreads();

    unsigned ball0, ball1;
    ball0 = s_ball[0];
    ball1 = s_ball[1];
    const int c0 = __popc(ball0);
    const int n  = c0 + __popc(ball1);

    if (tid < S_PER) {
        const unsigned myball = (warp == 0) ? ball0 : ball1;
        if (myball & (1u << lane)) {
            const int base = (warp == 0) ? 0 : c0;
            const int pos  = base + __popc(myball & ((1u << lane) - 1u));
            s_idx[pos] = (short)tid;
        }
    }
    __syncthreads();

    // ---- rare corner: slice all-zero. Full-batch mask scan to decide. ----
    bool sum_all = false;
    if (n == 0) {
        int csum = 0;
        #pragma unroll
        for (int j = 0; j < SS / 256; j++)
            csum += mask[b * SS + j * 256 + tid];
        #pragma unroll
        for (int o = 16; o > 0; o >>= 1)
            csum += __shfl_xor_sync(0xFFFFFFFFu, csum, o);
        __shared__ int s_g[8];
        if (lane == 0) s_g[warp] = csum;
        __syncthreads();
        int cg = 0;
        #pragma unroll
        for (int i = 0; i < 8; i++) cg += s_g[i];
        sum_all = (cg == 0);                          // batch truly empty
    }

    if (tid == 0) g_scnt[split * BB + b] = n;

    const float* rowbase = hidden + (size_t)b * SS * DD + (size_t)s0 * DD + (size_t)tid * 4;

    float ax = 0.0f, ay = 0.0f, az = 0.0f, aw = 0.0f;

    if (n > 0) {
        // ---- common path: gather-sum nonzero rows (streaming loads) ----
        int i = 0;
        for (; i + 4 <= n; i += 4) {
            const int r0 = s_idx[i + 0], r1 = s_idx[i + 1];
            const int r2 = s_idx[i + 2], r3 = s_idx[i + 3];
            const float4 v0 = __ldcs((const float4*)(rowbase + (size_t)r0 * DD));
            const float4 v1 = __ldcs((const float4*)(rowbase + (size_t)r1 * DD));
            const float4 v2 = __ldcs((const float4*)(rowbase + (size_t)r2 * DD));
            const float4 v3 = __ldcs((const float4*)(rowbase + (size_t)r3 * DD));
            ax += v0.x; ay += v0.y; az += v0.z; aw += v0.w;
            ax += v1.x; ay += v1.y; az += v1.z; aw += v1.w;
            ax += v2.x; ay += v2.y; az += v2.z; aw += v2.w;
            ax += v3.x; ay += v3.y; az += v3.z; aw += v3.w;
        }
        for (; i < n; i++) {
            const float4 v = __ldcs((const float4*)(rowbase + (size_t)s_idx[i] * DD));
            ax += v.x; ay += v.y; az += v.z; aw += v.w;
        }
    } else if (sum_all) {
        // ---- fallback: batch all-zero, sum ALL rows ----
        for (int i = 0; i + 4 <= S_PER; i += 4) {
            const float4 v0 = __ldcs((const float4*)(rowbase + (size_t)(i + 0) * DD));
            const float4 v1 = __ldcs((const float4*)(rowbase + (size_t)(i + 1) * DD));
            const float4 v2 = __ldcs((const float4*)(rowbase + (size_t)(i + 2) * DD));
            const float4 v3 = __ldcs((const float4*)(rowbase + (size_t)(i + 3) * DD));
            ax += v0.x; ay += v0.y; az += v0.z; aw += v0.w;
            ax += v1.x; ay += v1.y; az += v1.z; aw += v1.w;
            ax += v2.x; ay += v2.y; az += v2.z; aw += v2.w;
            ax += v3.x; ay += v3.y; az += v3.z; aw += v3.w;
        }
    }

    float4 p;
    p.x = ax; p.y = ay; p.z = az; p.w = aw;
    ((float4*)g_partial)[(size_t)(split * BB + b) * (DD / 4) + tid] = p;

    // ---- last-CTA-per-batch combine ----
    // RELEASE: bar.sync (all 256 threads' stores issued) -> cumulative
    // __threadfence (device-visible) -> tid0 arrive-atomic.
    __syncthreads();
    __threadfence();
    if (tid == 0)
        s_ticket = atomicAdd(&g_arrive[b], 1);
    __syncthreads();

    if (s_ticket == SPLITS - 1) {
        __threadfence();                              // ACQUIRE peers' partials
        if (tid == 0) g_arrive[b] = 0;                // reset for next replay

        // scnt prefetch (L2-hot broadcast) while partial loads go out below
        int cnt = 0;
        #pragma unroll
        for (int sp = 0; sp < SPLITS; sp++)
            cnt += g_scnt[sp * BB + b];
        const float inv = (cnt > 0) ? (1.0f / (float)cnt) : (1.0f / (float)SS);

        // own partial already in (ax..aw); read the other 31 in batches of 4
        // for bounded MLP without inflating the main path's register count.
        float cx = ax, cy = ay, cz = az, cw = aw;
        const float4* pb = (const float4*)g_partial;
        int sp = 0;
        #pragma unroll 1
        for (; sp + 4 <= SPLITS; sp += 4) {
            float4 q[4];
            #pragma unroll
            for (int j = 0; j < 4; j++) {
                const int s = sp + j;
                q[j] = (s == split)
                     ? make_float4(0.f, 0.f, 0.f, 0.f)
                     : __ldcg(pb + (size_t)(s * BB + b) * (DD / 4) + tid);
            }
            #pragma unroll
            for (int j = 0; j < 4; j++) {
                cx += q[j].x; cy += q[j].y; cz += q[j].z; cw += q[j].w;
            }
        }
        float4 o;
        o.x = cx * inv; o.y = cy * inv; o.z = cz * inv; o.w = cw * inv;
        ((float4*)out)[(size_t)b * (DD / 4) + tid] = o;
    }
}

// ---------------------------------------------------------------------------
extern "C" void kernel_launch(void* const* d_in, const int* in_sizes, int n_in,
                              void* d_out, int out_size) {
    const float* hidden = (const float*)d_in[0];
    const int*   mask   = (const int*)d_in[1];
    float*       out    = (float*)d_out;

    dim3 grid(SPLITS, BB);
    pool_kernel<<<grid, 256>>>(hidden, mask, out);
}

// round 17
// speedup vs baseline: 1.2184x; 1.2184x over previous
#include <cuda_runtime.h>
#include <cuda_bf16.h>
#include <cstdint>

#define BB 64
#define SS 2048
#define DD 1024
#define SPLITS 32
#define S_PER (SS / SPLITS)   // 64
#define WCNT (S_PER / 32)     // 2 warps cover the slice mask

// Scratch (allocation-free rule: __device__ globals)
__device__ int   g_scnt[SPLITS * BB];              // per-slice nonzero counts
__device__ float g_partial[SPLITS * BB * DD];      // 8 MB unweighted partials
__device__ int   g_arrive[BB];                     // zero-init; self-resetting

// ---------------------------------------------------------------------------
// Single fused kernel, SPLITS=32 -> 2048 tiles (~2 waves, wave-2 backfills
// variable-length wave-1 tiles). hidden reads use __ldcs (single-use stream).
// This is the exact R11 configuration (measured 49.66us) — R12's prologue/
// combine restructure regressed codegen (~1.9x issued instructions) and is
// reverted wholesale.
// grid = (SPLITS, BB), block = 256, one float4 of D per thread.
// ---------------------------------------------------------------------------
__global__ void __launch_bounds__(256)
pool_kernel(const float* __restrict__ hidden, const int* __restrict__ mask,
            float* __restrict__ out) {
    const int b     = blockIdx.y;
    const int split = blockIdx.x;
    const int s0    = split * S_PER;
    const int tid   = threadIdx.x;

    __shared__ short s_idx[S_PER];
    __shared__ int   s_warpcnt[WCNT];
    __shared__ int   s_ticket;

    // ---- own-slice mask read (threads 0..S_PER-1) + deterministic compaction
    const int warp = tid >> 5, lane = tid & 31;
    int mv = 0;
    if (tid < S_PER) {
        mv = mask[b * SS + s0 + tid];
        const unsigned ball = __ballot_sync(0xFFFFFFFFu, mv != 0);
        if (lane == 0) s_warpcnt[warp] = __popc(ball);
    }
    __syncthreads();

    int n = 0;
    #pragma unroll
    for (int i = 0; i < WCNT; i++) n += s_warpcnt[i];

    if (tid < S_PER) {
        const unsigned ball = __ballot_sync(0xFFFFFFFFu, mv != 0);
        int base = 0;
        #pragma unroll
        for (int i = 0; i < WCNT; i++) if (i < warp) base += s_warpcnt[i];
        if (mv != 0) {
            const int pos = base + __popc(ball & ((1u << lane) - 1u));
            s_idx[pos] = (short)tid;
        }
    }
    __syncthreads();

    // ---- rare corner: slice all-zero. Full-batch mask scan to decide. ----
    bool sum_all = false;
    if (n == 0) {
        int csum = 0;
        #pragma unroll
        for (int j = 0; j < SS / 256; j++)
            csum += mask[b * SS + j * 256 + tid];
        #pragma unroll
        for (int o = 16; o > 0; o >>= 1)
            csum += __shfl_xor_sync(0xFFFFFFFFu, csum, o);
        __shared__ int s_g[8];
        if (lane == 0) s_g[warp] = csum;
        __syncthreads();
        int cg = 0;
        #pragma unroll
        for (int i = 0; i < 8; i++) cg += s_g[i];
        sum_all = (cg == 0);                          // batch truly empty
    }

    if (tid == 0) g_scnt[split * BB + b] = n;

    const float* rowbase = hidden + (size_t)b * SS * DD + (size_t)s0 * DD + (size_t)tid * 4;

    float ax = 0.0f, ay = 0.0f, az = 0.0f, aw = 0.0f;

    if (n > 0) {
        // ---- common path: gather-sum nonzero rows (streaming loads) ----
        int i = 0;
        for (; i + 4 <= n; i += 4) {
            const int r0 = s_idx[i + 0], r1 = s_idx[i + 1];
            const int r2 = s_idx[i + 2], r3 = s_idx[i + 3];
            const float4 v0 = __ldcs((const float4*)(rowbase + (size_t)r0 * DD));
            const float4 v1 = __ldcs((const float4*)(rowbase + (size_t)r1 * DD));
            const float4 v2 = __ldcs((const float4*)(rowbase + (size_t)r2 * DD));
            const float4 v3 = __ldcs((const float4*)(rowbase + (size_t)r3 * DD));
            ax += v0.x; ay += v0.y; az += v0.z; aw += v0.w;
            ax += v1.x; ay += v1.y; az += v1.z; aw += v1.w;
            ax += v2.x; ay += v2.y; az += v2.z; aw += v2.w;
            ax += v3.x; ay += v3.y; az += v3.z; aw += v3.w;
        }
        for (; i < n; i++) {
            const float4 v = __ldcs((const float4*)(rowbase + (size_t)s_idx[i] * DD));
            ax += v.x; ay += v.y; az += v.z; aw += v.w;
        }
    } else if (sum_all) {
        // ---- fallback: batch all-zero, sum ALL rows ----
        for (int i = 0; i + 4 <= S_PER; i += 4) {
            const float4 v0 = __ldcs((const float4*)(rowbase + (size_t)(i + 0) * DD));
            const float4 v1 = __ldcs((const float4*)(rowbase + (size_t)(i + 1) * DD));
            const float4 v2 = __ldcs((const float4*)(rowbase + (size_t)(i + 2) * DD));
            const float4 v3 = __ldcs((const float4*)(rowbase + (size_t)(i + 3) * DD));
            ax += v0.x; ay += v0.y; az += v0.z; aw += v0.w;
            ax += v1.x; ay += v1.y; az += v1.z; aw += v1.w;
            ax += v2.x; ay += v2.y; az += v2.z; aw += v2.w;
            ax += v3.x; ay += v3.y; az += v3.z; aw += v3.w;
        }
    }

    float4 p;
    p.x = ax; p.y = ay; p.z = az; p.w = aw;
    ((float4*)g_partial)[(size_t)(split * BB + b) * (DD / 4) + tid] = p;

    // ---- last-CTA-per-batch combine ----
    // RELEASE: bar.sync (all 256 threads' stores issued) -> cumulative
    // __threadfence (device-visible) -> tid0 arrive-atomic.
    __syncthreads();
    __threadfence();
    if (tid == 0)
        s_ticket = atomicAdd(&g_arrive[b], 1);
    __syncthreads();

    if (s_ticket == SPLITS - 1) {
        __threadfence();                              // ACQUIRE peers' partials
        if (tid == 0) g_arrive[b] = 0;                // reset for next replay

        int cnt = 0;
        #pragma unroll
        for (int sp = 0; sp < SPLITS; sp++)
            cnt += g_scnt[sp * BB + b];
        const float inv = (cnt > 0) ? (1.0f / (float)cnt) : (1.0f / (float)SS);

        float cx = 0.0f, cy = 0.0f, cz = 0.0f, cw = 0.0f;
        #pragma unroll
        for (int sp = 0; sp < SPLITS; sp++) {
            const float4 v = ((const float4*)g_partial)[(size_t)(sp * BB + b) * (DD / 4) + tid];
            cx += v.x; cy += v.y; cz += v.z; cw += v.w;
        }
        float4 o;
        o.x = cx * inv; o.y = cy * inv; o.z = cz * inv; o.w = cw * inv;
        ((float4*)out)[(size_t)b * (DD / 4) + tid] = o;
    }
}

// ---------------------------------------------------------------------------
extern "C" void kernel_launch(void* const* d_in, const int* in_sizes, int n_in,
                              void* d_out, int out_size) {
    const float* hidden = (const float*)d_in[0];
    const int*   mask   = (const int*)d_in[1];
    float*       out    = (float*)d_out;

    dim3 grid(SPLITS, BB);
    pool_kernel<<<grid, 256>>>(hidden, mask, out);
}